// round 6
// baseline (speedup 1.0000x reference)
#include <cuda_runtime.h>

#define DM   1024          // model dim = N = K of every GEMM
#define MTOT 2048          // B*L rows
#define MINF (-3.402823466e38f)

// Scratch (allocation-free rule: __device__ globals)
__device__ float g_Q[MTOT * DM];
__device__ float g_K[MTOT * DM];
__device__ float g_V[MTOT * DM];
__device__ float g_A[MTOT * DM];

// ---------------------------------------------------------------------------
// SGEMM body: C[M=2048, N=1024] = X @ W^T + bias   (X:[2048,1024], W:[1024,1024])
// 128x128 tile, BK=16, 256 threads, 8x8 microtile.
// Double-buffered smem; mainloop has unconditional front-batched LDG.128
// prefetch (last slab peeled); one barrier per K-slab.
// ---------------------------------------------------------------------------

#define GEMM_COMPUTE_SLAB(P)                                                  \
    _Pragma("unroll")                                                         \
    for (int kk = 0; kk < 16; kk++) {                                         \
        float4 a0 = *(const float4*)&Xs[P][kk][ty * 4];                       \
        float4 a1 = *(const float4*)&Xs[P][kk][64 + ty * 4];                  \
        float4 b0 = *(const float4*)&Ws[P][kk][tx * 4];                       \
        float4 b1 = *(const float4*)&Ws[P][kk][64 + tx * 4];                  \
        float a[8] = {a0.x, a0.y, a0.z, a0.w, a1.x, a1.y, a1.z, a1.w};        \
        float bb[8] = {b0.x, b0.y, b0.z, b0.w, b1.x, b1.y, b1.z, b1.w};       \
        _Pragma("unroll")                                                     \
        for (int i = 0; i < 8; i++)                                           \
            _Pragma("unroll")                                                 \
            for (int j = 0; j < 8; j++) acc[i][j] += a[i] * bb[j];            \
    }

__device__ __forceinline__ void gemm_body(const float* __restrict__ X,
                                          const float* __restrict__ W,
                                          const float* __restrict__ bias,
                                          float* __restrict__ C)
{
    __shared__ float Xs[2][16][132];
    __shared__ float Ws[2][16][132];

    const int tid = threadIdx.x;
    const int tx = tid & 15, ty = tid >> 4;
    const int bm = blockIdx.y * 128;
    const int bn = blockIdx.x * 128;
    const int lr = tid >> 2;          // 0..63
    const int lc = (tid & 3) << 2;    // 0,4,8,12

    const float* Xp = X + (size_t)(bm + lr) * DM + lc;
    const float* Wp = W + (size_t)(bn + lr) * DM + lc;

    float acc[8][8];
#pragma unroll
    for (int i = 0; i < 8; i++)
#pragma unroll
        for (int j = 0; j < 8; j++) acc[i][j] = 0.f;

    // prologue: load slab 0 and stage into buffer 0
    {
        float4 xa = *(const float4*)(Xp);
        float4 xb = *(const float4*)(Xp + (size_t)64 * DM);
        float4 wa = *(const float4*)(Wp);
        float4 wb = *(const float4*)(Wp + (size_t)64 * DM);
        Xs[0][lc + 0][lr] = xa.x; Xs[0][lc + 1][lr] = xa.y; Xs[0][lc + 2][lr] = xa.z; Xs[0][lc + 3][lr] = xa.w;
        Xs[0][lc + 0][lr + 64] = xb.x; Xs[0][lc + 1][lr + 64] = xb.y; Xs[0][lc + 2][lr + 64] = xb.z; Xs[0][lc + 3][lr + 64] = xb.w;
        Ws[0][lc + 0][lr] = wa.x; Ws[0][lc + 1][lr] = wa.y; Ws[0][lc + 2][lr] = wa.z; Ws[0][lc + 3][lr] = wa.w;
        Ws[0][lc + 0][lr + 64] = wb.x; Ws[0][lc + 1][lr + 64] = wb.y; Ws[0][lc + 2][lr + 64] = wb.z; Ws[0][lc + 3][lr + 64] = wb.w;
    }
    __syncthreads();

    int p = 0;
    // mainloop over slabs; prefetch slab k0+16 unconditionally
    for (int k0 = 0; k0 < DM - 16; k0 += 16) {
        const int kn = k0 + 16;
        float4 xa = *(const float4*)(Xp + kn);
        float4 xb = *(const float4*)(Xp + kn + (size_t)64 * DM);
        float4 wa = *(const float4*)(Wp + kn);
        float4 wb = *(const float4*)(Wp + kn + (size_t)64 * DM);

        GEMM_COMPUTE_SLAB(p)

        const int np = p ^ 1;
        Xs[np][lc + 0][lr] = xa.x; Xs[np][lc + 1][lr] = xa.y; Xs[np][lc + 2][lr] = xa.z; Xs[np][lc + 3][lr] = xa.w;
        Xs[np][lc + 0][lr + 64] = xb.x; Xs[np][lc + 1][lr + 64] = xb.y; Xs[np][lc + 2][lr + 64] = xb.z; Xs[np][lc + 3][lr + 64] = xb.w;
        Ws[np][lc + 0][lr] = wa.x; Ws[np][lc + 1][lr] = wa.y; Ws[np][lc + 2][lr] = wa.z; Ws[np][lc + 3][lr] = wa.w;
        Ws[np][lc + 0][lr + 64] = wb.x; Ws[np][lc + 1][lr + 64] = wb.y; Ws[np][lc + 2][lr + 64] = wb.z; Ws[np][lc + 3][lr + 64] = wb.w;
        __syncthreads();
        p = np;
    }
    // peeled final slab
    GEMM_COMPUTE_SLAB(p)

    // epilogue
#pragma unroll
    for (int i = 0; i < 8; i++) {
        int r = bm + ((i < 4) ? (ty * 4 + i) : (64 + ty * 4 + i - 4));
#pragma unroll
        for (int jh = 0; jh < 2; jh++) {
            int c = bn + ((jh == 0) ? (tx * 4) : (64 + tx * 4));
            float4 o;
            o.x = acc[i][jh * 4 + 0] + bias[c + 0];
            o.y = acc[i][jh * 4 + 1] + bias[c + 1];
            o.z = acc[i][jh * 4 + 2] + bias[c + 2];
            o.w = acc[i][jh * 4 + 3] + bias[c + 3];
            *(float4*)&C[(size_t)r * DM + c] = o;
        }
    }
}

// QKV projections batched over blockIdx.z (fills the chip in one launch)
__global__ __launch_bounds__(256, 2) void gemm_qkv(
    const float* __restrict__ q, const float* __restrict__ k, const float* __restrict__ v,
    const float* __restrict__ Wq, const float* __restrict__ Wk, const float* __restrict__ Wv,
    const float* __restrict__ bq, const float* __restrict__ bk, const float* __restrict__ bv)
{
    int z = blockIdx.z;
    const float* X = (z == 0) ? q : (z == 1) ? k : v;
    const float* W = (z == 0) ? Wq : (z == 1) ? Wk : Wv;
    const float* b = (z == 0) ? bq : (z == 1) ? bk : bv;
    float* C = (z == 0) ? g_Q : (z == 1) ? g_K : g_V;
    gemm_body(X, W, b, C);
}

// Output projection: out = g_A @ Wo^T + bo
__global__ __launch_bounds__(256, 2) void gemm_out(const float* __restrict__ Wo,
                                                   const float* __restrict__ bo,
                                                   float* __restrict__ out)
{
    gemm_body(g_A, Wo, bo, out);
}

// ---------------------------------------------------------------------------
// Flash attention, fp32. One block = (b, h, 64 query rows). 256 threads (16x16).
// Key tiles of 32, software-pipelined: K/V LDGs for tile kt+1 are issued before
// the S/softmax compute of tile kt (3 barriers/tile, latency fully hidden).
// Mask semantics replicate the reference EXACTLY:
// score = qk*scale + (keep ? 0 : FLT_MIN_NEG); dead rows -> uniform softmax.
// ---------------------------------------------------------------------------
__global__ __launch_bounds__(256) void attn_kernel(const int* __restrict__ amask)
{
    __shared__ float Qs[64][68];
    __shared__ float Ks[32][68];
    __shared__ float Vs[32][68];
    __shared__ float Ps[32][68];
    __shared__ unsigned char pmk[1024];

    const int tid = threadIdx.x;
    const int tx = tid & 15, ty = tid >> 4;
    const int qt = blockIdx.x & 15;
    const int bh = blockIdx.x >> 4;
    const int h = bh & 15, b = bh >> 4;

    const float* Qb = g_Q + (size_t)b * 1024 * DM + h * 64;
    const float* Kb = g_K + (size_t)b * 1024 * DM + h * 64;
    const float* Vb = g_V + (size_t)b * 1024 * DM + h * 64;

    for (int i = tid; i < 1024; i += 256)
        pmk[i] = (amask[b * 1024 + i] != 0) ? 1 : 0;

    for (int i = tid; i < 1024; i += 256) {
        int r = i >> 4, ch = i & 15;
        *(float4*)&Qs[r][ch * 4] = *(const float4*)&Qb[(size_t)(qt * 64 + r) * DM + ch * 4];
    }
    __syncthreads();

    float m[4], l[4], oacc[4][4];
#pragma unroll
    for (int i = 0; i < 4; i++) {
        m[i] = MINF; l[i] = 0.f;
#pragma unroll
        for (int j = 0; j < 4; j++) oacc[i][j] = 0.f;
    }
    const int qr0 = qt * 64 + ty * 4;

    // If the whole q-block is alive (prefix mask), tiles above the diagonal and
    // tiles fully in padding contribute exactly 0 to both numerator and
    // denominator -> safe to skip. If any row is dead, we must cover ALL 1024
    // columns (dead rows take uniform softmax over the full length).
    const bool alive = (pmk[qt * 64 + 63] != 0);
    const int ktEnd = alive ? ((qt * 64 + 63) >> 5) : 31;

    // Per-thread staging slice: 4 float4 covering K (i<512) then V (i>=512).
    float4 pf[4];
#pragma unroll
    for (int u = 0; u < 4; u++) {
        const int i = tid + u * 256;
        const int r = (i >> 4) & 31, ch = i & 15;
        pf[u] = (i < 512)
            ? *(const float4*)&Kb[(size_t)r * DM + ch * 4]
            : *(const float4*)&Vb[(size_t)r * DM + ch * 4];
    }

    for (int kt = 0; kt <= ktEnd; kt++) {
        if (alive && pmk[kt * 32] == 0) break;   // block-uniform prefix mask
        __syncthreads();                          // prior PV reads (Ps,Vs) done
        // stage prefetched tile kt
#pragma unroll
        for (int u = 0; u < 4; u++) {
            const int i = tid + u * 256;
            const int r = (i >> 4) & 31, ch = i & 15;
            if (i < 512) *(float4*)&Ks[r][ch * 4] = pf[u];
            else         *(float4*)&Vs[r][ch * 4] = pf[u];
        }
        __syncthreads();

        // issue LDGs for tile kt+1 (clamped in-bounds); lands after PV barrier
        {
            const int pkt = (kt + 1 <= 31) ? kt + 1 : 31;
#pragma unroll
            for (int u = 0; u < 4; u++) {
                const int i = tid + u * 256;
                const int r = (i >> 4) & 31, ch = i & 15;
                pf[u] = (i < 512)
                    ? *(const float4*)&Kb[(size_t)(pkt * 32 + r) * DM + ch * 4]
                    : *(const float4*)&Vb[(size_t)(pkt * 32 + r) * DM + ch * 4];
            }
        }

        // S = Q K^T  (4 rows x 2 cols per thread)
        float sacc[4][2] = {{0.f, 0.f}, {0.f, 0.f}, {0.f, 0.f}, {0.f, 0.f}};
#pragma unroll
        for (int d = 0; d < 64; d += 4) {
            float4 k0 = *(const float4*)&Ks[tx * 2 + 0][d];
            float4 k1 = *(const float4*)&Ks[tx * 2 + 1][d];
#pragma unroll
            for (int i = 0; i < 4; i++) {
                float4 qv = *(const float4*)&Qs[ty * 4 + i][d];
                sacc[i][0] += qv.x * k0.x + qv.y * k0.y + qv.z * k0.z + qv.w * k0.w;
                sacc[i][1] += qv.x * k1.x + qv.y * k1.y + qv.z * k1.z + qv.w * k1.w;
            }
        }

        const int kc0 = kt * 32 + tx * 2;
        const bool pk0 = pmk[kc0] != 0;
        const bool pk1 = pmk[kc0 + 1] != 0;
        float p[4][2];
#pragma unroll
        for (int i = 0; i < 4; i++) {
            const int qr = qr0 + i;
            const bool pq = pmk[qr] != 0;
            float s0 = sacc[i][0] * 0.125f + ((pq && pk0 && (kc0     <= qr)) ? 0.f : MINF);
            float s1 = sacc[i][1] * 0.125f + ((pq && pk1 && (kc0 + 1 <= qr)) ? 0.f : MINF);
            float tm = fmaxf(s0, s1);
            tm = fmaxf(tm, __shfl_xor_sync(0xffffffffu, tm, 1));
            tm = fmaxf(tm, __shfl_xor_sync(0xffffffffu, tm, 2));
            tm = fmaxf(tm, __shfl_xor_sync(0xffffffffu, tm, 4));
            tm = fmaxf(tm, __shfl_xor_sync(0xffffffffu, tm, 8));
            float mn = fmaxf(m[i], tm);
            float p0 = __expf(s0 - mn);
            float p1 = __expf(s1 - mn);
            float ts = p0 + p1;
            ts += __shfl_xor_sync(0xffffffffu, ts, 1);
            ts += __shfl_xor_sync(0xffffffffu, ts, 2);
            ts += __shfl_xor_sync(0xffffffffu, ts, 4);
            ts += __shfl_xor_sync(0xffffffffu, ts, 8);
            float corr = __expf(m[i] - mn);
            l[i] = l[i] * corr + ts;
            m[i] = mn;
#pragma unroll
            for (int j = 0; j < 4; j++) oacc[i][j] *= corr;
            p[i][0] = p0; p[i][1] = p1;
        }
        // P transposed into smem for the PV outer product
#pragma unroll
        for (int i = 0; i < 4; i++) {
            Ps[tx * 2 + 0][ty * 4 + i] = p[i][0];
            Ps[tx * 2 + 1][ty * 4 + i] = p[i][1];
        }
        __syncthreads();                          // Ps visible (Ks reads done too)

        // O += P V
#pragma unroll
        for (int c = 0; c < 32; c++) {
            float4 pa = *(const float4*)&Ps[c][ty * 4];
            float4 vb = *(const float4*)&Vs[c][tx * 4];
            float pav[4] = {pa.x, pa.y, pa.z, pa.w};
            float vbv[4] = {vb.x, vb.y, vb.z, vb.w};
#pragma unroll
            for (int i = 0; i < 4; i++)
#pragma unroll
                for (int j = 0; j < 4; j++) oacc[i][j] += pav[i] * vbv[j];
        }
    }

#pragma unroll
    for (int i = 0; i < 4; i++) {
        float inv = 1.f / l[i];
        float4 o;
        o.x = oacc[i][0] * inv; o.y = oacc[i][1] * inv;
        o.z = oacc[i][2] * inv; o.w = oacc[i][3] * inv;
        size_t row = (size_t)(b * 1024 + qt * 64 + ty * 4 + i);
        *(float4*)&g_A[row * DM + h * 64 + tx * 4] = o;
    }
}

// ---------------------------------------------------------------------------
extern "C" void kernel_launch(void* const* d_in, const int* in_sizes, int n_in,
                              void* d_out, int out_size)
{
    const float* q  = (const float*)d_in[0];
    const float* k  = (const float*)d_in[1];
    const float* v  = (const float*)d_in[2];
    const int*   am = (const int*)  d_in[3];
    const float* Wq = (const float*)d_in[4];
    const float* bq = (const float*)d_in[5];
    const float* Wk = (const float*)d_in[6];
    const float* bk = (const float*)d_in[7];
    const float* Wv = (const float*)d_in[8];
    const float* bv = (const float*)d_in[9];
    const float* Wo = (const float*)d_in[10];
    const float* bo = (const float*)d_in[11];
    float* out = (float*)d_out;

    dim3 gqkv(DM / 128, MTOT / 128, 3);   // (8, 16, 3)
    gemm_qkv<<<gqkv, 256>>>(q, k, v, Wq, Wk, Wv, bq, bk, bv);
    attn_kernel<<<512, 256>>>(am);
    dim3 go(DM / 128, MTOT / 128);        // (8, 16)
    gemm_out<<<go, 256>>>(Wo, bo, out);
}

// round 8
// speedup vs baseline: 1.1081x; 1.1081x over previous
#include <cuda_runtime.h>

#define DM   1024
#define MTOT 2048
#define MINF (-3.402823466e38f)

// Scratch (allocation-free rule: __device__ globals)
__device__ float g_Q[MTOT * DM];
__device__ float g_K[MTOT * DM];
__device__ float g_V[MTOT * DM];
__device__ float g_A[MTOT * DM];
__device__ float g_P[6 * MTOT * DM];   // split-K partials (6 slabs of 8MB)

// ---------------------------------------------------------------------------
// SGEMM partial: C[2048,1024] = X[:, kBeg:kEnd] @ W[:, kBeg:kEnd]^T  (no bias)
// 128x128 tile, BK=16, 256 threads, 8x8 microtile, double-buffered smem,
// unconditional front-batched LDG prefetch, last slab peeled.
// ---------------------------------------------------------------------------
#define GEMM_COMPUTE_SLAB(P)                                                  \
    _Pragma("unroll")                                                         \
    for (int kk = 0; kk < 16; kk++) {                                         \
        float4 a0 = *(const float4*)&Xs[P][kk][ty * 4];                       \
        float4 a1 = *(const float4*)&Xs[P][kk][64 + ty * 4];                  \
        float4 b0 = *(const float4*)&Ws[P][kk][tx * 4];                       \
        float4 b1 = *(const float4*)&Ws[P][kk][64 + tx * 4];                  \
        float a[8] = {a0.x, a0.y, a0.z, a0.w, a1.x, a1.y, a1.z, a1.w};        \
        float bb[8] = {b0.x, b0.y, b0.z, b0.w, b1.x, b1.y, b1.z, b1.w};       \
        _Pragma("unroll")                                                     \
        for (int i = 0; i < 8; i++)                                           \
            _Pragma("unroll")                                                 \
            for (int j = 0; j < 8; j++) acc[i][j] += a[i] * bb[j];            \
    }

__device__ __forceinline__ void gemm_part(const float* __restrict__ X,
                                          const float* __restrict__ W,
                                          float* __restrict__ C,
                                          int kBeg, int kEnd)
{
    __shared__ float Xs[2][16][132];
    __shared__ float Ws[2][16][132];

    const int tid = threadIdx.x;
    const int tx = tid & 15, ty = tid >> 4;
    const int bm = blockIdx.y * 128;
    const int bn = blockIdx.x * 128;
    const int lr = tid >> 2;
    const int lc = (tid & 3) << 2;

    const float* Xp = X + (size_t)(bm + lr) * DM + lc;
    const float* Wp = W + (size_t)(bn + lr) * DM + lc;

    float acc[8][8];
#pragma unroll
    for (int i = 0; i < 8; i++)
#pragma unroll
        for (int j = 0; j < 8; j++) acc[i][j] = 0.f;

    {   // prologue: slab kBeg into buffer 0
        float4 xa = *(const float4*)(Xp + kBeg);
        float4 xb = *(const float4*)(Xp + kBeg + (size_t)64 * DM);
        float4 wa = *(const float4*)(Wp + kBeg);
        float4 wb = *(const float4*)(Wp + kBeg + (size_t)64 * DM);
        Xs[0][lc + 0][lr] = xa.x; Xs[0][lc + 1][lr] = xa.y; Xs[0][lc + 2][lr] = xa.z; Xs[0][lc + 3][lr] = xa.w;
        Xs[0][lc + 0][lr + 64] = xb.x; Xs[0][lc + 1][lr + 64] = xb.y; Xs[0][lc + 2][lr + 64] = xb.z; Xs[0][lc + 3][lr + 64] = xb.w;
        Ws[0][lc + 0][lr] = wa.x; Ws[0][lc + 1][lr] = wa.y; Ws[0][lc + 2][lr] = wa.z; Ws[0][lc + 3][lr] = wa.w;
        Ws[0][lc + 0][lr + 64] = wb.x; Ws[0][lc + 1][lr + 64] = wb.y; Ws[0][lc + 2][lr + 64] = wb.z; Ws[0][lc + 3][lr + 64] = wb.w;
    }
    __syncthreads();

    int p = 0;
    for (int k0 = kBeg; k0 < kEnd - 16; k0 += 16) {
        const int kn = k0 + 16;
        float4 xa = *(const float4*)(Xp + kn);
        float4 xb = *(const float4*)(Xp + kn + (size_t)64 * DM);
        float4 wa = *(const float4*)(Wp + kn);
        float4 wb = *(const float4*)(Wp + kn + (size_t)64 * DM);

        GEMM_COMPUTE_SLAB(p)

        const int np = p ^ 1;
        Xs[np][lc + 0][lr] = xa.x; Xs[np][lc + 1][lr] = xa.y; Xs[np][lc + 2][lr] = xa.z; Xs[np][lc + 3][lr] = xa.w;
        Xs[np][lc + 0][lr + 64] = xb.x; Xs[np][lc + 1][lr + 64] = xb.y; Xs[np][lc + 2][lr + 64] = xb.z; Xs[np][lc + 3][lr + 64] = xb.w;
        Ws[np][lc + 0][lr] = wa.x; Ws[np][lc + 1][lr] = wa.y; Ws[np][lc + 2][lr] = wa.z; Ws[np][lc + 3][lr] = wa.w;
        Ws[np][lc + 0][lr + 64] = wb.x; Ws[np][lc + 1][lr + 64] = wb.y; Ws[np][lc + 2][lr + 64] = wb.z; Ws[np][lc + 3][lr + 64] = wb.w;
        __syncthreads();
        p = np;
    }
    GEMM_COMPUTE_SLAB(p)

#pragma unroll
    for (int i = 0; i < 8; i++) {
        int r = bm + ((i < 4) ? (ty * 4 + i) : (64 + ty * 4 + i - 4));
#pragma unroll
        for (int jh = 0; jh < 2; jh++) {
            int c = bn + ((jh == 0) ? (tx * 4) : (64 + tx * 4));
            float4 o;
            o.x = acc[i][jh * 4 + 0];
            o.y = acc[i][jh * 4 + 1];
            o.z = acc[i][jh * 4 + 2];
            o.w = acc[i][jh * 4 + 3];
            *(float4*)&C[(size_t)r * DM + c] = o;
        }
    }
}

// QKV split-K=2: z' = half*3 + matrix (grid.z = 6)
__global__ __launch_bounds__(256, 2) void gemm_qkv_split(
    const float* __restrict__ q, const float* __restrict__ k, const float* __restrict__ v,
    const float* __restrict__ Wq, const float* __restrict__ Wk, const float* __restrict__ Wv)
{
    const int z6 = blockIdx.z;
    const int z = z6 % 3, half = z6 / 3;
    const float* X = (z == 0) ? q : (z == 1) ? k : v;
    const float* W = (z == 0) ? Wq : (z == 1) ? Wk : Wv;
    float* C = g_P + (size_t)z6 * MTOT * DM;
    gemm_part(X, W, C, half * 512, half * 512 + 512);
}

// combine: g_{Q,K,V} = P[z] + P[z+3] + bias  (fixed order -> deterministic)
__global__ __launch_bounds__(256) void qkv_combine(
    const float* __restrict__ bq, const float* __restrict__ bk, const float* __restrict__ bv)
{
    const size_t i4 = (size_t)blockIdx.x * 256 + threadIdx.x;   // 1572864 total
    const int z = (int)(i4 >> 19);
    const size_t j4 = i4 & 524287;
    const int col4 = (int)(j4 & 255);
    const float4 a = ((const float4*)g_P)[(size_t)z * 524288 + j4];
    const float4 c = ((const float4*)g_P)[(size_t)(z + 3) * 524288 + j4];
    const float* bias = (z == 0) ? bq : (z == 1) ? bk : bv;
    const float4 bb = ((const float4*)bias)[col4];
    float* outp = (z == 0) ? g_Q : (z == 1) ? g_K : g_V;
    float4 o;
    o.x = a.x + c.x + bb.x; o.y = a.y + c.y + bb.y;
    o.z = a.z + c.z + bb.z; o.w = a.w + c.w + bb.w;
    ((float4*)outp)[j4] = o;
}

// OUT split-K=4 (grid.z = 4)
__global__ __launch_bounds__(256, 2) void gemm_out_split(const float* __restrict__ Wo)
{
    const int qtr = blockIdx.z;
    float* C = g_P + (size_t)qtr * MTOT * DM;
    gemm_part(g_A, Wo, C, qtr * 256, qtr * 256 + 256);
}

__global__ __launch_bounds__(256) void out_combine(const float* __restrict__ bo,
                                                   float* __restrict__ outp)
{
    const size_t j4 = (size_t)blockIdx.x * 256 + threadIdx.x;   // 524288 total
    const int col4 = (int)(j4 & 255);
    const float4 s0 = ((const float4*)g_P)[0 * 524288 + j4];
    const float4 s1 = ((const float4*)g_P)[1 * 524288 + j4];
    const float4 s2 = ((const float4*)g_P)[2 * 524288 + j4];
    const float4 s3 = ((const float4*)g_P)[3 * 524288 + j4];
    const float4 bb = ((const float4*)bo)[col4];
    float4 o;
    o.x = ((s0.x + s1.x) + (s2.x + s3.x)) + bb.x;
    o.y = ((s0.y + s1.y) + (s2.y + s3.y)) + bb.y;
    o.z = ((s0.z + s1.z) + (s2.z + s3.z)) + bb.z;
    o.w = ((s0.w + s1.w) + (s2.w + s3.w)) + bb.w;
    ((float4*)outp)[j4] = o;
}

// ---------------------------------------------------------------------------
// Flash attention fp32. Block = (b, h, 64 q-rows); 256 thr; k-tile 64.
// Microtile 4q x 4k per thread; k-columns strided {tx, tx+16, tx+32, tx+48}
// (low-conflict smem). S: 8 LDS.128 / 64 FMA; PV: 2 LDS.128 / 32 FMA.
// Dynamic smem: Qs|Ks|Vs|Ps each 64x68 floats (69,632 B total).
// Mask semantics identical to reference: s = qk*scale + (keep?0:FLT_MIN_NEG);
// dead rows -> uniform softmax over full length.
// ---------------------------------------------------------------------------
__global__ __launch_bounds__(256) void attn_kernel(const int* __restrict__ amask)
{
    extern __shared__ float sm[];
    float* Qs = sm;                 // [64][68]
    float* Ks = sm + 64 * 68;       // [64][68]
    float* Vs = sm + 2 * 64 * 68;   // [64][68]
    float* Ps = sm + 3 * 64 * 68;   // [64][68]  (P transposed: [kcol][qrow])
    __shared__ unsigned char pmk[1024];

    const int tid = threadIdx.x;
    const int tx = tid & 15, ty = tid >> 4;
    const int qt = blockIdx.x & 15;
    const int bh = blockIdx.x >> 4;
    const int h = bh & 15, b = bh >> 4;

    const float* Qb = g_Q + (size_t)b * 1024 * DM + h * 64;
    const float* Kb = g_K + (size_t)b * 1024 * DM + h * 64;
    const float* Vb = g_V + (size_t)b * 1024 * DM + h * 64;

    for (int i = tid; i < 1024; i += 256)
        pmk[i] = (amask[b * 1024 + i] != 0) ? 1 : 0;

    for (int i = tid; i < 1024; i += 256) {
        int r = i >> 4, ch = i & 15;
        *(float4*)&Qs[r * 68 + ch * 4] = *(const float4*)&Qb[(size_t)(qt * 64 + r) * DM + ch * 4];
    }
    __syncthreads();

    float m[4], l[4], oacc[4][4];
#pragma unroll
    for (int i = 0; i < 4; i++) {
        m[i] = MINF; l[i] = 0.f;
#pragma unroll
        for (int j = 0; j < 4; j++) oacc[i][j] = 0.f;
    }
    const int qr0 = qt * 64 + ty * 4;
    const bool alive = (pmk[qt * 64 + 63] != 0);
    const int ktEnd = alive ? qt : 15;

    for (int kt = 0; kt <= ktEnd; kt++) {
        if (alive && pmk[kt * 64] == 0) break;   // prefix mask: rest is padding
        __syncthreads();                          // prior PV reads (Ps,Vs) done
        for (int i = tid; i < 2048; i += 256) {
            int r = (i >> 4) & 63, ch = i & 15;
            if (i < 1024)
                *(float4*)&Ks[r * 68 + ch * 4] = *(const float4*)&Kb[(size_t)(kt * 64 + r) * DM + ch * 4];
            else
                *(float4*)&Vs[r * 68 + ch * 4] = *(const float4*)&Vb[(size_t)(kt * 64 + r) * DM + ch * 4];
        }
        __syncthreads();

        // S = Q K^T : 4 q-rows x 4 strided k-cols per thread
        float sacc[4][4];
#pragma unroll
        for (int i = 0; i < 4; i++)
#pragma unroll
            for (int u = 0; u < 4; u++) sacc[i][u] = 0.f;

#pragma unroll
        for (int d = 0; d < 64; d += 4) {
            float4 kv[4];
#pragma unroll
            for (int u = 0; u < 4; u++)
                kv[u] = *(const float4*)&Ks[(tx + 16 * u) * 68 + d];
#pragma unroll
            for (int i = 0; i < 4; i++) {
                float4 qv = *(const float4*)&Qs[(ty * 4 + i) * 68 + d];
#pragma unroll
                for (int u = 0; u < 4; u++)
                    sacc[i][u] += qv.x * kv[u].x + qv.y * kv[u].y + qv.z * kv[u].z + qv.w * kv[u].w;
            }
        }

        // mask + online softmax (reduction over 16 tx lanes)
#pragma unroll
        for (int i = 0; i < 4; i++) {
            const int qr = qr0 + i;
            const bool pq = pmk[qr] != 0;
            float s[4];
#pragma unroll
            for (int u = 0; u < 4; u++) {
                const int kc = kt * 64 + tx + 16 * u;
                const bool keep = pq && (pmk[kc] != 0) && (kc <= qr);
                s[u] = sacc[i][u] * 0.125f + (keep ? 0.f : MINF);
            }
            float tm = fmaxf(fmaxf(s[0], s[1]), fmaxf(s[2], s[3]));
            tm = fmaxf(tm, __shfl_xor_sync(0xffffffffu, tm, 1));
            tm = fmaxf(tm, __shfl_xor_sync(0xffffffffu, tm, 2));
            tm = fmaxf(tm, __shfl_xor_sync(0xffffffffu, tm, 4));
            tm = fmaxf(tm, __shfl_xor_sync(0xffffffffu, tm, 8));
            const float mn = fmaxf(m[i], tm);
            float p0 = __expf(s[0] - mn);
            float p1 = __expf(s[1] - mn);
            float p2 = __expf(s[2] - mn);
            float p3 = __expf(s[3] - mn);
            float ts = (p0 + p1) + (p2 + p3);
            ts += __shfl_xor_sync(0xffffffffu, ts, 1);
            ts += __shfl_xor_sync(0xffffffffu, ts, 2);
            ts += __shfl_xor_sync(0xffffffffu, ts, 4);
            ts += __shfl_xor_sync(0xffffffffu, ts, 8);
            const float corr = __expf(m[i] - mn);
            l[i] = l[i] * corr + ts;
            m[i] = mn;
#pragma unroll
            for (int j = 0; j < 4; j++) oacc[i][j] *= corr;
            Ps[(tx +  0) * 68 + ty * 4 + i] = p0;
            Ps[(tx + 16) * 68 + ty * 4 + i] = p1;
            Ps[(tx + 32) * 68 + ty * 4 + i] = p2;
            Ps[(tx + 48) * 68 + ty * 4 + i] = p3;
        }
        __syncthreads();                          // Ps visible; Ks reads done

        // O += P V : per k, 2 LDS.128 for 16 FMA
#pragma unroll
        for (int c = 0; c < 64; c++) {
            float4 pa = *(const float4*)&Ps[c * 68 + ty * 4];
            float4 vb = *(const float4*)&Vs[c * 68 + tx * 4];
            float pav[4] = {pa.x, pa.y, pa.z, pa.w};
            float vbv[4] = {vb.x, vb.y, vb.z, vb.w};
#pragma unroll
            for (int i = 0; i < 4; i++)
#pragma unroll
                for (int j = 0; j < 4; j++) oacc[i][j] += pav[i] * vbv[j];
        }
    }

#pragma unroll
    for (int i = 0; i < 4; i++) {
        const float inv = 1.f / l[i];
        float4 o;
        o.x = oacc[i][0] * inv; o.y = oacc[i][1] * inv;
        o.z = oacc[i][2] * inv; o.w = oacc[i][3] * inv;
        const size_t row = (size_t)(b * 1024 + qr0 + i);
        *(float4*)&g_A[row * DM + h * 64 + tx * 4] = o;
    }
}

// ---------------------------------------------------------------------------
#define ATTN_SMEM (4 * 64 * 68 * 4)

extern "C" void kernel_launch(void* const* d_in, const int* in_sizes, int n_in,
                              void* d_out, int out_size)
{
    const float* q  = (const float*)d_in[0];
    const float* k  = (const float*)d_in[1];
    const float* v  = (const float*)d_in[2];
    const int*   am = (const int*)  d_in[3];
    const float* Wq = (const float*)d_in[4];
    const float* bq = (const float*)d_in[5];
    const float* Wk = (const float*)d_in[6];
    const float* bk = (const float*)d_in[7];
    const float* Wv = (const float*)d_in[8];
    const float* bv = (const float*)d_in[9];
    const float* Wo = (const float*)d_in[10];
    const float* bo = (const float*)d_in[11];
    float* out = (float*)d_out;

    cudaFuncSetAttribute(attn_kernel, cudaFuncAttributeMaxDynamicSharedMemorySize, ATTN_SMEM);

    gemm_qkv_split<<<dim3(8, 16, 6), 256>>>(q, k, v, Wq, Wk, Wv);
    qkv_combine<<<6144, 256>>>(bq, bk, bv);
    attn_kernel<<<512, 256, ATTN_SMEM>>>(am);
    gemm_out_split<<<dim3(8, 16, 4), 256>>>(Wo);
    out_combine<<<2048, 256>>>(bo, out);
}